// round 16
// baseline (speedup 1.0000x reference)
#include <cuda_runtime.h>
#include <cuda_fp16.h>
#include <math.h>

#define TT   12
#define NN   50000
#define NH   (NN * 128)
#define MT512 98            // ceil(50000/512) ; grid.x=14 -> exactly 7 tiles/block
#define CSLOT 6500000       // 98*8*512*16 = 6,422,528 rounded up

// ================= scratch =================
// floats: c0 c1 (2*CSLOT) | h fp16 4 bufs (2NH fl) | hfin hw agg (3NH) | dinv 65536 |
// bar 1024 | half tail: B0 (8*144*64) B1 (8*272*64) xpad (12*NN*16) ones (NN*16)
__device__ float g_scratch[2 * CSLOT + 5 * NH + 65536 + 1024 + 5400000];

// ================= PTX helpers (portable, sm_80+) =================
__device__ __forceinline__ unsigned smem_u32(const void* p) {
    unsigned a;
    asm("{ .reg .u64 t; cvta.to.shared.u64 t, %1; cvt.u32.u64 %0, t; }" : "=r"(a) : "l"(p));
    return a;
}
__device__ __forceinline__ void cp16(unsigned dst, const void* src) {
    asm volatile("cp.async.cg.shared.global [%0], [%1], 16;" :: "r"(dst), "l"(src));
}
#define CP_COMMIT() asm volatile("cp.async.commit_group;" ::: "memory")
#define CP_WAIT0()  asm volatile("cp.async.wait_group 0;" ::: "memory")
#define CP_WAIT1()  asm volatile("cp.async.wait_group 1;" ::: "memory")
#define CP_WAIT2()  asm volatile("cp.async.wait_group 2;" ::: "memory")
#define CP_WAIT3()  asm volatile("cp.async.wait_group 3;" ::: "memory")

#define LDSM_X4(r0, r1, r2, r3, a) \
    asm volatile("ldmatrix.sync.aligned.m8n8.x4.shared.b16 {%0,%1,%2,%3}, [%4];" \
        : "=r"(r0), "=r"(r1), "=r"(r2), "=r"(r3) : "r"(a))

#define LDSM_X4T(r0, r1, r2, r3, a) \
    asm volatile("ldmatrix.sync.aligned.m8n8.x4.trans.shared.b16 {%0,%1,%2,%3}, [%4];" \
        : "=r"(r0), "=r"(r1), "=r"(r2), "=r"(r3) : "r"(a))

#define MMA16816F16(d, a, b) \
    asm volatile("mma.sync.aligned.m16n8k16.row.col.f32.f16.f16.f32 " \
        "{%0,%1,%2,%3}, {%4,%5,%6,%7}, {%8,%9}, {%0,%1,%2,%3};" \
        : "+f"((d)[0]), "+f"((d)[1]), "+f"((d)[2]), "+f"((d)[3]) \
        : "r"((a)[0]), "r"((a)[1]), "r"((a)[2]), "r"((a)[3]), "r"((b)[0]), "r"((b)[1]))

__device__ __forceinline__ float sigf(float z) { return __fdividef(1.0f, 1.0f + __expf(-z)); }
__device__ __forceinline__ float tanhf_(float z) { return __fdividef(2.0f, 1.0f + __expf(-2.0f * z)) - 1.0f; }

// ================= prep kernels =================
__global__ void zero_k(float* p, int n) {
    int i = blockIdx.x * blockDim.x + threadIdx.x;
    if (i < n) p[i] = 0.0f;
}

// xpad[t][n][16] = [x0, x1, 1, 0...]; t==12 slot -> ones[n][16] = [1, 0...]
__global__ void prep_aug(const float* __restrict__ x,
                         __half* __restrict__ xp, __half* __restrict__ on) {
    int idx = blockIdx.x * blockDim.x + threadIdx.x;
    if (idx >= 13 * NN * 16) return;
    int col = idx & 15;
    int rest = idx >> 4;
    int n = rest % NN;
    int t = rest / NN;
    float v = 0.f;
    if (t < 12) {
        if (col < 2) v = x[((size_t)n * TT + t) * 2 + col];
        else if (col == 2) v = 1.0f;
        xp[((size_t)t * NN + n) * 16 + col] = __float2half(v);
    } else {
        if (col == 0) v = 1.0f;
        on[(size_t)n * 16 + col] = __float2half(v);
    }
}

// staged B layout: [y(8)][k(BROWS)][col(64)], col = g*16 + jl, ro = g*128 + y*16 + jl
__global__ void prep_B0(const float* __restrict__ Whh0, const float* __restrict__ Wih0,
                        const float* __restrict__ bih0, const float* __restrict__ bhh0,
                        __half* __restrict__ B) {
    int idx = blockIdx.x * blockDim.x + threadIdx.x;      // 8*144*64
    if (idx >= 8 * 144 * 64) return;
    int y = idx / (144 * 64);
    int rem = idx - y * (144 * 64);
    int k = rem >> 6, col = rem & 63;
    int ro = (col >> 4) * 128 + y * 16 + (col & 15);
    float w = 0.f;
    if (k < 128) w = Whh0[ro * 128 + k];
    else if (k == 128) w = Wih0[ro * 2 + 0];
    else if (k == 129) w = Wih0[ro * 2 + 1];
    else if (k == 130) w = bih0[ro] + bhh0[ro];
    B[idx] = __float2half(w);
}

__global__ void prep_B1(const float* __restrict__ Wih1, const float* __restrict__ Whh1,
                        const float* __restrict__ bih1, const float* __restrict__ bhh1,
                        __half* __restrict__ B) {
    int idx = blockIdx.x * blockDim.x + threadIdx.x;      // 8*272*64
    if (idx >= 8 * 272 * 64) return;
    int y = idx / (272 * 64);
    int rem = idx - y * (272 * 64);
    int k = rem >> 6, col = rem & 63;
    int ro = (col >> 4) * 128 + y * 16 + (col & 15);
    float w = 0.f;
    if (k < 128) w = Wih1[ro * 128 + k];
    else if (k < 256) w = Whh1[ro * 128 + (k - 128)];
    else if (k == 256) w = bih1[ro] + bhh1[ro];
    B[idx] = __float2half(w);
}

__global__ void deg_init(float* deg) {
    int i = blockIdx.x * blockDim.x + threadIdx.x;
    if (i < NN) deg[i] = 1.0f;
}
__global__ void deg_count(const int* __restrict__ dst, float* deg, int E) {
    int i = blockIdx.x * blockDim.x + threadIdx.x;
    if (i < E) atomicAdd(&deg[dst[i]], 1.0f);
}
__global__ void deg_rsqrt(float* deg) {
    int i = blockIdx.x * blockDim.x + threadIdx.x;
    if (i < NN) deg[i] = rsqrtf(deg[i]);
}

__global__ void recon_h(const __half* __restrict__ hh, float* __restrict__ out) {
    int i = blockIdx.x * blockDim.x + threadIdx.x;
    if (i < NH) out[i] = __half2float(hh[i]);
}

// ================= persistent LSTM =================
// grid (14, 8), 512 thr. Block owns tiles m in [x*7, x*7+7), 64 gate-cols (y).
// smem: B0 [0, 20736) | B1 [20736, 59904) | rings [59904, 158208)
// Group barrier: 8 blocks sharing x sync via monotonic counter in global mem.
#define B1_OFF 20736u
#define RING_OFF 59904u

__device__ __forceinline__ void group_barrier(int* cnt, int target) {
    __syncthreads();
    if (threadIdx.x == 0) {
        __threadfence();
        atomicAdd(cnt, 1);
        while (*(volatile int*)cnt < target) __nanosleep(100);
        __threadfence();
    }
    __syncthreads();
}

// One layer-step phase over this block's 7 m-tiles.
// kphys = j < skipStart ? j : j + skipLen  (skips zero-h segments at t=0)
template <int NK>
__device__ __forceinline__ void lstm_phase(
    unsigned sb, unsigned bOff,
    const __half* __restrict__ A0, const __half* __restrict__ A1,
    const __half* __restrict__ AG,
    int nk, int skipStart, int skipLen,
    float* __restrict__ c, __half* __restrict__ Oh) {
    int tid = threadIdx.x, lane = tid & 31, wid = tid >> 5;
    int x = blockIdx.x, y = blockIdx.y;
    unsigned ring = sb + RING_OFF + (unsigned)wid * 6144u;   // 4 stages x 1536B
    unsigned a_ad[2];
#pragma unroll
    for (int mt = 0; mt < 2; mt++)
        a_ad[mt] = (unsigned)((mt * 16 + (lane & 15)) * 48 + (lane >> 4) * 16);
    int bkk = ((lane >> 3) & 1) * 8 + (lane & 7);
    unsigned bcol8 = (unsigned)((lane >> 4) * 8 * 2);
    int q = lane & 3;

    for (int mi = 0; mi < 7; mi++) {
        int m = x * 7 + mi;
        int nbase = m * 512;
        int arow = nbase + wid * 32 + lane;
        if (arow >= NN) arow = NN - 1;

        auto loadA = [&](int j) {
            int kn = (j < skipStart) ? j : j + skipLen;
            const __half* H;
            size_t so;
            if (kn < 8)                   { H = A0; so = (size_t)arow * 128 + kn * 16; }
            else if (NK == 17 && kn < 16) { H = A1; so = (size_t)arow * 128 + (kn - 8) * 16; }
            else                          { H = AG; so = (size_t)arow * 16; }
            unsigned d = ring + (unsigned)((j & 3) * 1536 + lane * 48);
            cp16(d,       H + so);
            cp16(d + 16u, H + so + 8);
            CP_COMMIT();
        };

        float acc[2][8][4];
#pragma unroll
        for (int mt = 0; mt < 2; mt++)
#pragma unroll
            for (int nf = 0; nf < 8; nf++)
#pragma unroll
                for (int i = 0; i < 4; i++) acc[mt][nf][i] = 0.f;

        loadA(0);
        if (1 < nk) loadA(1);
        if (2 < nk) loadA(2);

        for (int j = 0; j < nk; j++) {
            if (j + 3 < nk)      { loadA(j + 3); CP_WAIT3(); }
            else if (j + 2 < nk) { CP_WAIT2(); }
            else if (j + 1 < nk) { CP_WAIT1(); }
            else                 { CP_WAIT0(); }

            int kphys = (j < skipStart) ? j : j + skipLen;
            unsigned abuf = ring + (unsigned)((j & 3) * 1536);
            unsigned ah[2][4];
#pragma unroll
            for (int mt = 0; mt < 2; mt++)
                LDSM_X4(ah[mt][0], ah[mt][1], ah[mt][2], ah[mt][3], abuf + a_ad[mt]);

            unsigned bbase_k = sb + bOff + (unsigned)((kphys * 16 + bkk) * 144);
#pragma unroll
            for (int half = 0; half < 2; half++) {
                unsigned bh[4][2];
#pragma unroll
                for (int np = 0; np < 2; np++) {
                    unsigned ad = bbase_k + (unsigned)(half * 64 + np * 32) + bcol8;
                    LDSM_X4T(bh[np * 2][0], bh[np * 2][1], bh[np * 2 + 1][0], bh[np * 2 + 1][1], ad);
                }
#pragma unroll
                for (int mt = 0; mt < 2; mt++)
#pragma unroll
                    for (int nf4 = 0; nf4 < 4; nf4++)
                        MMA16816F16(acc[mt][half * 4 + nf4], ah[mt], bh[nf4]);
            }
        }

        // ---- in-register epilogue; c in coalesced slot layout ----
        size_t cbase = (((size_t)m * 8 + y) * 512 + tid) * 16;
        int jb0 = y * 16 + q * 2;
#pragma unroll
        for (int mt = 0; mt < 2; mt++)
#pragma unroll
            for (int rp = 0; rp < 2; rp++) {
                int n = nbase + wid * 32 + mt * 16 + rp * 8 + (lane >> 2);
                float4 cv = *(const float4*)(c + cbase + (mt * 8 + rp * 4));
                float cres[4], hres[4];
#pragma unroll
                for (int jli = 0; jli < 4; jli++) {
                    int jh = jli >> 1;
                    int par = jli & 1;
                    int ridx = rp * 2 + par;
                    float zi = acc[mt][0 + jh][ridx];
                    float zf = acc[mt][2 + jh][ridx];
                    float zg = acc[mt][4 + jh][ridx];
                    float zo = acc[mt][6 + jh][ridx];
                    float cp_ = (&cv.x)[jli];
                    float cn = sigf(zf) * cp_ + sigf(zi) * tanhf_(zg);
                    cres[jli] = cn;
                    hres[jli] = sigf(zo) * tanhf_(cn);
                }
                *(float4*)(c + cbase + (mt * 8 + rp * 4)) =
                    make_float4(cres[0], cres[1], cres[2], cres[3]);
                if (n < NN) {
                    *(__half2*)(Oh + (size_t)n * 128 + jb0) =
                        __floats2half2_rn(hres[0], hres[1]);
                    *(__half2*)(Oh + (size_t)n * 128 + jb0 + 8) =
                        __floats2half2_rn(hres[2], hres[3]);
                }
            }
    }
}

__global__ __launch_bounds__(512, 1)
void lstm_persist(__half* h0a, __half* h0b, __half* h1a, __half* h1b,
                  const __half* __restrict__ xp, const __half* __restrict__ on,
                  const __half* __restrict__ B0_st, const __half* __restrict__ B1_st,
                  float* c0, float* c1, int* bar) {
    extern __shared__ char smem[];
    unsigned sb = smem_u32(smem);
    int tid = threadIdx.x;
    int x = blockIdx.x, y = blockIdx.y;

    // ---- load both B slices once ----
    {
        size_t b0base = (size_t)y * 144 * 64;
        for (int i = tid; i < 144 * 8; i += 512) {
            int k = i >> 3, seg = i & 7;
            cp16(sb + (unsigned)(k * 144 + seg * 16),
                 B0_st + b0base + (size_t)k * 64 + seg * 8);
        }
        size_t b1base = (size_t)y * 272 * 64;
        for (int i = tid; i < 272 * 8; i += 512) {
            int k = i >> 3, seg = i & 7;
            cp16(sb + B1_OFF + (unsigned)(k * 144 + seg * 16),
                 B1_st + b1base + (size_t)k * 64 + seg * 8);
        }
        CP_COMMIT();
        CP_WAIT0();
    }
    __syncthreads();

    int* cnt = bar + x * 32;
    int bstep = 0;
    __half* h0buf[2] = { h0a, h0b };
    __half* h1buf[2] = { h1a, h1b };
    int p = 0;
    for (int t = 0; t < TT; t++) {
        // layer 0: A = [h0 | xpad_t]; t=0 skips zero h0 (ksteps 0..7)
        lstm_phase<9>(sb, 0u,
                      h0buf[p], (const __half*)nullptr, xp + (size_t)t * NN * 16,
                      t == 0 ? 1 : 9, t == 0 ? 0 : 9, t == 0 ? 8 : 0,
                      c0, h0buf[1 - p]);
        bstep++;
        group_barrier(cnt, 8 * bstep);
        // layer 1: A = [h0_t | h1_prev | aug]; t=0 skips zero h1 (ksteps 8..15)
        lstm_phase<17>(sb, B1_OFF,
                       h0buf[1 - p], h1buf[p], on,
                       t == 0 ? 9 : 17, t == 0 ? 8 : 17, t == 0 ? 8 : 0,
                       c1, h1buf[1 - p]);
        if (t < TT - 1) {
            bstep++;
            group_barrier(cnt, 8 * bstep);
        }
        p ^= 1;
    }
}

// ================= GCN (fp32, proven) =================
__global__ __launch_bounds__(256)
void gcn_gemm(const float* __restrict__ A, const float* __restrict__ W,
              float* __restrict__ out, int relu) {
    __shared__ float As[16][68];
    __shared__ float Bs[16][128];
    int tid = threadIdx.x;
    int ty = tid >> 4, tx = tid & 15;
    int nbase = blockIdx.x * 64;
    float acc[4][8];
#pragma unroll
    for (int i = 0; i < 4; i++)
#pragma unroll
        for (int j = 0; j < 8; j++) acc[i][j] = 0.f;
    int a_row = tid >> 2;
    int a_k4 = (tid & 3) * 4;
    for (int kc = 0; kc < 128; kc += 16) {
        int n = nbase + a_row;
        float4 v = make_float4(0.f, 0.f, 0.f, 0.f);
        if (n < NN) v = *(const float4*)(A + (size_t)n * 128 + kc + a_k4);
        if (relu) {
            v.x = fmaxf(v.x, 0.f); v.y = fmaxf(v.y, 0.f);
            v.z = fmaxf(v.z, 0.f); v.w = fmaxf(v.w, 0.f);
        }
        As[a_k4 + 0][a_row] = v.x; As[a_k4 + 1][a_row] = v.y;
        As[a_k4 + 2][a_row] = v.z; As[a_k4 + 3][a_row] = v.w;
#pragma unroll
        for (int r8 = 0; r8 < 8; r8++) {
            int idx = r8 * 256 + tid;
            int k = idx >> 7, jj = idx & 127;
            Bs[k][jj] = W[(kc + k) * 128 + jj];
        }
        __syncthreads();
#pragma unroll
        for (int k = 0; k < 16; k++) {
            float a[4], b[8];
#pragma unroll
            for (int i = 0; i < 4; i++) a[i] = As[k][ty * 4 + i];
#pragma unroll
            for (int jj = 0; jj < 8; jj++) b[jj] = Bs[k][tx * 8 + jj];
#pragma unroll
            for (int i = 0; i < 4; i++)
#pragma unroll
                for (int jj = 0; jj < 8; jj++) acc[i][jj] = fmaf(a[i], b[jj], acc[i][jj]);
        }
        __syncthreads();
    }
#pragma unroll
    for (int i = 0; i < 4; i++) {
        int n = nbase + ty * 4 + i;
        if (n >= NN) continue;
#pragma unroll
        for (int jj = 0; jj < 8; jj++) out[(size_t)n * 128 + tx * 8 + jj] = acc[i][jj];
    }
}

__global__ void gcn_init(const float* __restrict__ hW, const float* __restrict__ bvec,
                         const float* __restrict__ dinv, float* __restrict__ agg) {
    int idx = blockIdx.x * blockDim.x + threadIdx.x;
    if (idx >= NN * 128) return;
    int n = idx >> 7, jj = idx & 127;
    float di = dinv[n];
    agg[idx] = bvec[jj] + hW[idx] * di * di;
}

__global__ void gcn_agg(const float* __restrict__ hW, const int* __restrict__ src,
                        const int* __restrict__ dst, const float* __restrict__ dinv,
                        float* __restrict__ agg, int E) {
    int gw = (blockIdx.x * blockDim.x + threadIdx.x) >> 5;
    int lane = threadIdx.x & 31;
    if (gw >= E) return;
    int s = src[gw], d = dst[gw];
    float w = dinv[s] * dinv[d];
    float4 v = ((const float4*)(hW + (size_t)s * 128))[lane];
    float* p = agg + (size_t)d * 128 + lane * 4;
    atomicAdd(p + 0, v.x * w);
    atomicAdd(p + 1, v.y * w);
    atomicAdd(p + 2, v.z * w);
    atomicAdd(p + 3, v.w * w);
}

__global__ void gcn_gemm12(const float* __restrict__ A, const float* __restrict__ W2,
                           float* __restrict__ out12) {
    int warp = (blockIdx.x * blockDim.x + threadIdx.x) >> 5;
    int lane = threadIdx.x & 31;
    if (warp >= NN) return;
    float acc[12];
#pragma unroll
    for (int jj = 0; jj < 12; jj++) acc[jj] = 0.f;
    for (int k = lane; k < 128; k += 32) {
        float a = fmaxf(A[(size_t)warp * 128 + k], 0.f);
#pragma unroll
        for (int jj = 0; jj < 12; jj++) acc[jj] = fmaf(a, W2[k * 12 + jj], acc[jj]);
    }
#pragma unroll
    for (int jj = 0; jj < 12; jj++) {
        float v = acc[jj];
#pragma unroll
        for (int o = 16; o; o >>= 1) v += __shfl_down_sync(0xffffffffu, v, o);
        if (lane == 0) out12[(size_t)warp * 12 + jj] = v;
    }
}

__global__ void gcn_init12(const float* __restrict__ hW12, const float* __restrict__ b2,
                           const float* __restrict__ dinv, float* __restrict__ out) {
    int idx = blockIdx.x * blockDim.x + threadIdx.x;
    if (idx >= NN * 12) return;
    int n = idx / 12, jj = idx - n * 12;
    float di = dinv[n];
    out[idx] = b2[jj] + hW12[idx] * di * di;
}

__global__ void gcn_agg12(const float* __restrict__ hW12, const int* __restrict__ src,
                          const int* __restrict__ dst, const float* __restrict__ dinv,
                          float* __restrict__ out, int E) {
    int idx = blockIdx.x * blockDim.x + threadIdx.x;
    int e = idx >> 4;
    int jj = idx & 15;
    if (e >= E || jj >= 12) return;
    int s = src[e], d = dst[e];
    float w = dinv[s] * dinv[d];
    atomicAdd(&out[(size_t)d * 12 + jj], hW12[(size_t)s * 12 + jj] * w);
}

// ================= launch =================
extern "C" void kernel_launch(void* const* d_in, const int* in_sizes, int n_in,
                              void* d_out, int out_size) {
    const float* x    = (const float*)d_in[0];
    const int*   ei   = (const int*)d_in[1];
    const float* Wih0 = (const float*)d_in[2];
    const float* Whh0 = (const float*)d_in[3];
    const float* bih0 = (const float*)d_in[4];
    const float* bhh0 = (const float*)d_in[5];
    const float* Wih1 = (const float*)d_in[6];
    const float* Whh1 = (const float*)d_in[7];
    const float* bih1 = (const float*)d_in[8];
    const float* bhh1 = (const float*)d_in[9];
    const float* W0   = (const float*)d_in[10];
    const float* b0   = (const float*)d_in[11];
    const float* W1   = (const float*)d_in[12];
    const float* b1   = (const float*)d_in[13];
    const float* W2   = (const float*)d_in[14];
    const float* b2   = (const float*)d_in[15];
    float* out = (float*)d_out;

    int E = in_sizes[1] / 2;
    const int* src = ei;
    const int* dst = ei + E;

    float* S;
    cudaGetSymbolAddress((void**)&S, g_scratch);
    float* c0 = S;
    float* c1 = S + (size_t)CSLOT;
    __half* HF = (__half*)(S + 2 * (size_t)CSLOT);
    __half* h0[2] = { HF + 0 * (size_t)NH, HF + 1 * (size_t)NH };
    __half* h1[2] = { HF + 2 * (size_t)NH, HF + 3 * (size_t)NH };
    float* hfin = S + 2 * (size_t)CSLOT + 2 * (size_t)NH;
    float* hw   = hfin + (size_t)NH;
    float* agg  = hw + (size_t)NH;
    float* dinv = agg + (size_t)NH;
    float* barF = dinv + 65536;
    int*   bar  = (int*)barF;
    __half* Q = (__half*)(barF + 1024);
    __half* B0  = Q;  Q += 8 * 144 * 64;
    __half* B1  = Q;  Q += 8 * 272 * 64;
    __half* xp  = Q;  Q += (size_t)12 * NN * 16;
    __half* on  = Q;  Q += (size_t)NN * 16;

    zero_k<<<(2 * CSLOT + 255) / 256, 256>>>(S, 2 * CSLOT);
    zero_k<<<4, 256>>>(barF, 1024);
    prep_aug<<<(13 * NN * 16 + 255) / 256, 256>>>(x, xp, on);
    prep_B0<<<(8 * 144 * 64 + 255) / 256, 256>>>(Whh0, Wih0, bih0, bhh0, B0);
    prep_B1<<<(8 * 272 * 64 + 255) / 256, 256>>>(Wih1, Whh1, bih1, bhh1, B1);

    const int SMP = 158208;   // B0 20736 + B1 39168 + rings 98304
    cudaFuncSetAttribute(lstm_persist, cudaFuncAttributeMaxDynamicSharedMemorySize, SMP);

    lstm_persist<<<dim3(14, 8), 512, SMP>>>(h0[0], h0[1], h1[0], h1[1],
                                            xp, on, B0, B1, c0, c1, bar);

    recon_h<<<(NH + 255) / 256, 256>>>(h1[0], hfin);

    deg_init<<<(NN + 255) / 256, 256>>>(dinv);
    deg_count<<<(E + 255) / 256, 256>>>(dst, dinv, E);
    deg_rsqrt<<<(NN + 255) / 256, 256>>>(dinv);

    gcn_gemm<<<(NN + 63) / 64, 256>>>(hfin, W0, hw, 0);
    gcn_init<<<(NN * 128 + 255) / 256, 256>>>(hw, b0, dinv, agg);
    gcn_agg<<<(E + 7) / 8, 256>>>(hw, src, dst, dinv, agg, E);
    gcn_gemm<<<(NN + 63) / 64, 256>>>(agg, W1, hw, 1);
    gcn_init<<<(NN * 128 + 255) / 256, 256>>>(hw, b1, dinv, agg);
    gcn_agg<<<(E + 7) / 8, 256>>>(hw, src, dst, dinv, agg, E);
    gcn_gemm12<<<(NN * 32 + 255) / 256, 256>>>(agg, W2, hw);
    gcn_init12<<<(NN * 12 + 255) / 256, 256>>>(hw, b2, dinv, out);
    gcn_agg12<<<((size_t)E * 16 + 255) / 256, 256>>>(hw, src, dst, dinv, out, E);
}

// round 17
// speedup vs baseline: 1.1444x; 1.1444x over previous
#include <cuda_runtime.h>
#include <cuda_fp16.h>
#include <math.h>

#define TT   12
#define NN   50000
#define NH   (NN * 128)
#define MT512 98            // ceil(50000/512)
#define CSLOT 6500000       // 98*8*512*16 = 6,422,528 rounded up

// ================= scratch =================
// floats: c0 c1 (2*CSLOT) | h fp16 4 bufs (2NH fl) | hfin hw agg (3NH) | dinv 65536 |
// half tail: B0 (8*144*64) B1 (8*272*64) Bt0 (8*144*64) xpad (12*NN*16) ones (NN*16)
__device__ float g_scratch[2 * CSLOT + 5 * NH + 65536 + 5400000];

// ================= PTX helpers (portable, sm_80+) =================
__device__ __forceinline__ unsigned smem_u32(const void* p) {
    unsigned a;
    asm("{ .reg .u64 t; cvta.to.shared.u64 t, %1; cvt.u32.u64 %0, t; }" : "=r"(a) : "l"(p));
    return a;
}
__device__ __forceinline__ void cp16(unsigned dst, const void* src) {
    asm volatile("cp.async.cg.shared.global [%0], [%1], 16;" :: "r"(dst), "l"(src));
}
#define CP_COMMIT() asm volatile("cp.async.commit_group;" ::: "memory")
#define CP_WAIT0()  asm volatile("cp.async.wait_group 0;" ::: "memory")
#define CP_WAIT1()  asm volatile("cp.async.wait_group 1;" ::: "memory")
#define CP_WAIT2()  asm volatile("cp.async.wait_group 2;" ::: "memory")
#define CP_WAIT3()  asm volatile("cp.async.wait_group 3;" ::: "memory")

#define LDSM_X4(r0, r1, r2, r3, a) \
    asm volatile("ldmatrix.sync.aligned.m8n8.x4.shared.b16 {%0,%1,%2,%3}, [%4];" \
        : "=r"(r0), "=r"(r1), "=r"(r2), "=r"(r3) : "r"(a))

#define LDSM_X4T(r0, r1, r2, r3, a) \
    asm volatile("ldmatrix.sync.aligned.m8n8.x4.trans.shared.b16 {%0,%1,%2,%3}, [%4];" \
        : "=r"(r0), "=r"(r1), "=r"(r2), "=r"(r3) : "r"(a))

#define MMA16816F16(d, a, b) \
    asm volatile("mma.sync.aligned.m16n8k16.row.col.f32.f16.f16.f32 " \
        "{%0,%1,%2,%3}, {%4,%5,%6,%7}, {%8,%9}, {%0,%1,%2,%3};" \
        : "+f"((d)[0]), "+f"((d)[1]), "+f"((d)[2]), "+f"((d)[3]) \
        : "r"((a)[0]), "r"((a)[1]), "r"((a)[2]), "r"((a)[3]), "r"((b)[0]), "r"((b)[1]))

// single-MUFU tanh (sm_75+); sigmoid via tanh identity (1 MUFU + 1 FMA)
__device__ __forceinline__ float tanh_fast(float x) {
    float r;
    asm("tanh.approx.f32 %0, %1;" : "=f"(r) : "f"(x));
    return r;
}
__device__ __forceinline__ float sigf(float z) { return fmaf(tanh_fast(z * 0.5f), 0.5f, 0.5f); }
__device__ __forceinline__ float tanhf_(float z) { return tanh_fast(z); }

// ================= prep kernels =================
__global__ void zero_k(float* p, int n) {
    int i = blockIdx.x * blockDim.x + threadIdx.x;
    if (i < n) p[i] = 0.0f;
}

// xpad[t][n][16] = [x0, x1, 1, 0...]; t==12 slot -> ones[n][16] = [1, 0...]
__global__ void prep_aug(const float* __restrict__ x,
                         __half* __restrict__ xp, __half* __restrict__ on) {
    int idx = blockIdx.x * blockDim.x + threadIdx.x;
    if (idx >= 13 * NN * 16) return;
    int col = idx & 15;
    int rest = idx >> 4;
    int n = rest % NN;
    int t = rest / NN;
    float v = 0.f;
    if (t < 12) {
        if (col < 2) v = x[((size_t)n * TT + t) * 2 + col];
        else if (col == 2) v = 1.0f;
        xp[((size_t)t * NN + n) * 16 + col] = __float2half(v);
    } else {
        if (col == 0) v = 1.0f;
        on[(size_t)n * 16 + col] = __float2half(v);
    }
}

// staged B layout: [y(8)][k(BROWS)][col(64)], col = g*16 + jl, ro = g*128 + y*16 + jl
__global__ void prep_B0(const float* __restrict__ Whh0, const float* __restrict__ Wih0,
                        const float* __restrict__ bih0, const float* __restrict__ bhh0,
                        __half* __restrict__ B) {
    int idx = blockIdx.x * blockDim.x + threadIdx.x;      // 8*144*64
    if (idx >= 8 * 144 * 64) return;
    int y = idx / (144 * 64);
    int rem = idx - y * (144 * 64);
    int k = rem >> 6, col = rem & 63;
    int ro = (col >> 4) * 128 + y * 16 + (col & 15);
    float w = 0.f;
    if (k < 128) w = Whh0[ro * 128 + k];
    else if (k == 128) w = Wih0[ro * 2 + 0];
    else if (k == 129) w = Wih0[ro * 2 + 1];
    else if (k == 130) w = bih0[ro] + bhh0[ro];
    B[idx] = __float2half(w);
}

__global__ void prep_B1(const float* __restrict__ Wih1, const float* __restrict__ Whh1,
                        const float* __restrict__ bih1, const float* __restrict__ bhh1,
                        __half* __restrict__ B) {
    int idx = blockIdx.x * blockDim.x + threadIdx.x;      // 8*272*64
    if (idx >= 8 * 272 * 64) return;
    int y = idx / (272 * 64);
    int rem = idx - y * (272 * 64);
    int k = rem >> 6, col = rem & 63;
    int ro = (col >> 4) * 128 + y * 16 + (col & 15);
    float w = 0.f;
    if (k < 128) w = Wih1[ro * 128 + k];
    else if (k < 256) w = Whh1[ro * 128 + (k - 128)];
    else if (k == 256) w = bih1[ro] + bhh1[ro];
    B[idx] = __float2half(w);
}

__global__ void prep_B1t0(const float* __restrict__ Wih1,
                          const float* __restrict__ bih1, const float* __restrict__ bhh1,
                          __half* __restrict__ B) {
    int idx = blockIdx.x * blockDim.x + threadIdx.x;      // 8*144*64
    if (idx >= 8 * 144 * 64) return;
    int y = idx / (144 * 64);
    int rem = idx - y * (144 * 64);
    int k = rem >> 6, col = rem & 63;
    int ro = (col >> 4) * 128 + y * 16 + (col & 15);
    float w = 0.f;
    if (k < 128) w = Wih1[ro * 128 + k];
    else if (k == 128) w = bih1[ro] + bhh1[ro];
    B[idx] = __float2half(w);
}

__global__ void deg_init(float* deg) {
    int i = blockIdx.x * blockDim.x + threadIdx.x;
    if (i < NN) deg[i] = 1.0f;
}
__global__ void deg_count(const int* __restrict__ dst, float* deg, int E) {
    int i = blockIdx.x * blockDim.x + threadIdx.x;
    if (i < E) atomicAdd(&deg[dst[i]], 1.0f);
}
__global__ void deg_rsqrt(float* deg) {
    int i = blockIdx.x * blockDim.x + threadIdx.x;
    if (i < NN) deg[i] = rsqrtf(deg[i]);
}

__global__ void recon_h(const __half* __restrict__ hh, float* __restrict__ out) {
    int i = blockIdx.x * blockDim.x + threadIdx.x;
    if (i < NH) out[i] = __half2float(hh[i]);
}

// ================= LSTM step: fp16 single chain, 16 m-warps x 64 cols =================
// grid (18, 8). 512 thr = 16 warps, 32 rows/warp; m-tile 512 rows. Zero m-loop barriers.
// B resident smem [k][64] stride 144B (fp16). A: warp-private 4-stage cp.async ring
// (stage 1536B, rows stride 48B). Aug columns fold x and bias into the GEMM.
// c lives in a private slot layout -> fully coalesced float4 access.
template <int NK>
__global__ __launch_bounds__(512, 1)
void lstm_mma(const __half* __restrict__ A0, const __half* __restrict__ A1,
              const __half* __restrict__ AG,
              const __half* __restrict__ B_st,
              int kstart,
              float* __restrict__ c,
              __half* __restrict__ Oh) {
    extern __shared__ char smem[];
    unsigned sb = smem_u32(smem);
    const int BROWS = NK * 16;
    const unsigned BSZ = (unsigned)(BROWS * 144);
    int tid = threadIdx.x, lane = tid & 31, wid = tid >> 5;
    int y = blockIdx.y;

    // ---- B resident load (once) ----
    {
        size_t bbase = (size_t)y * BROWS * 64;
        for (int i = tid; i < BROWS * 8; i += 512) {
            int k = i >> 3, seg = i & 7;
            cp16(sb + (unsigned)(k * 144 + seg * 16),
                 B_st + bbase + (size_t)k * 64 + seg * 8);
        }
        CP_COMMIT();
        CP_WAIT0();
    }
    __syncthreads();

    unsigned ring = sb + BSZ + (unsigned)wid * 6144u;   // 4 stages x 1536B
    unsigned a_ad[2];
#pragma unroll
    for (int mt = 0; mt < 2; mt++)
        a_ad[mt] = (unsigned)((mt * 16 + (lane & 15)) * 48 + (lane >> 4) * 16);
    int bkk = ((lane >> 3) & 1) * 8 + (lane & 7);
    unsigned bcol8 = (unsigned)((lane >> 4) * 8 * 2);

    int q = lane & 3;

    for (int m = blockIdx.x; m < MT512; m += gridDim.x) {
        int nbase = m * 512;
        int arow = nbase + wid * 32 + lane;
        if (arow >= NN) arow = NN - 1;

        auto loadA = [&](int kn) {
            const __half* H;
            size_t so;
            if (kn < 8)                   { H = A0; so = (size_t)arow * 128 + kn * 16; }
            else if (NK == 17 && kn < 16) { H = A1; so = (size_t)arow * 128 + (kn - 8) * 16; }
            else                          { H = AG; so = (size_t)arow * 16; }
            unsigned d = ring + (unsigned)((kn & 3) * 1536 + lane * 48);
            cp16(d,       H + so);
            cp16(d + 16u, H + so + 8);
            CP_COMMIT();
        };

        float acc[2][8][4];
#pragma unroll
        for (int mt = 0; mt < 2; mt++)
#pragma unroll
            for (int nf = 0; nf < 8; nf++)
#pragma unroll
                for (int i = 0; i < 4; i++) acc[mt][nf][i] = 0.f;

        // prologue: 3 chunks in flight
        loadA(kstart);
        if (kstart + 1 < NK) loadA(kstart + 1);
        if (kstart + 2 < NK) loadA(kstart + 2);

        for (int kc = kstart; kc < NK; kc++) {
            if (kc + 3 < NK)      { loadA(kc + 3); CP_WAIT3(); }
            else if (kc + 2 < NK) { CP_WAIT2(); }
            else if (kc + 1 < NK) { CP_WAIT1(); }
            else                  { CP_WAIT0(); }

            unsigned abuf = ring + (unsigned)((kc & 3) * 1536);
            unsigned ah[2][4];
#pragma unroll
            for (int mt = 0; mt < 2; mt++)
                LDSM_X4(ah[mt][0], ah[mt][1], ah[mt][2], ah[mt][3], abuf + a_ad[mt]);

            unsigned bbase_k = sb + (unsigned)((kc * 16 + bkk) * 144);
#pragma unroll
            for (int half = 0; half < 2; half++) {
                unsigned bh[4][2];
#pragma unroll
                for (int np = 0; np < 2; np++) {
                    unsigned ad = bbase_k + (unsigned)(half * 64 + np * 32) + bcol8;
                    LDSM_X4T(bh[np * 2][0], bh[np * 2][1], bh[np * 2 + 1][0], bh[np * 2 + 1][1], ad);
                }
#pragma unroll
                for (int mt = 0; mt < 2; mt++)
#pragma unroll
                    for (int nf4 = 0; nf4 < 4; nf4++)
                        MMA16816F16(acc[mt][half * 4 + nf4], ah[mt], bh[nf4]);
            }
        }

        // ---- in-register epilogue; c in coalesced slot layout ----
        size_t cbase = (((size_t)m * 8 + y) * 512 + tid) * 16;
        int jb0 = y * 16 + q * 2;
#pragma unroll
        for (int mt = 0; mt < 2; mt++)
#pragma unroll
            for (int rp = 0; rp < 2; rp++) {
                int n = nbase + wid * 32 + mt * 16 + rp * 8 + (lane >> 2);
                float4 cv = *(const float4*)(c + cbase + (mt * 8 + rp * 4));
                float cres[4], hres[4];
#pragma unroll
                for (int jli = 0; jli < 4; jli++) {
                    int jh = jli >> 1;
                    int par = jli & 1;
                    int ridx = rp * 2 + par;
                    float zi = acc[mt][0 + jh][ridx];
                    float zf = acc[mt][2 + jh][ridx];
                    float zg = acc[mt][4 + jh][ridx];
                    float zo = acc[mt][6 + jh][ridx];
                    float cp_ = (&cv.x)[jli];
                    float cn = sigf(zf) * cp_ + sigf(zi) * tanhf_(zg);
                    cres[jli] = cn;
                    hres[jli] = sigf(zo) * tanhf_(cn);
                }
                *(float4*)(c + cbase + (mt * 8 + rp * 4)) =
                    make_float4(cres[0], cres[1], cres[2], cres[3]);
                if (n < NN) {
                    *(__half2*)(Oh + (size_t)n * 128 + jb0) =
                        __floats2half2_rn(hres[0], hres[1]);
                    *(__half2*)(Oh + (size_t)n * 128 + jb0 + 8) =
                        __floats2half2_rn(hres[2], hres[3]);
                }
            }
        // no __syncthreads: ring warp-private, B read-only, epilogue register-local
    }
}

// ================= GCN (fp32, proven) =================
__global__ __launch_bounds__(256)
void gcn_gemm(const float* __restrict__ A, const float* __restrict__ W,
              float* __restrict__ out, int relu) {
    __shared__ float As[16][68];
    __shared__ float Bs[16][128];
    int tid = threadIdx.x;
    int ty = tid >> 4, tx = tid & 15;
    int nbase = blockIdx.x * 64;
    float acc[4][8];
#pragma unroll
    for (int i = 0; i < 4; i++)
#pragma unroll
        for (int j = 0; j < 8; j++) acc[i][j] = 0.f;
    int a_row = tid >> 2;
    int a_k4 = (tid & 3) * 4;
    for (int kc = 0; kc < 128; kc += 16) {
        int n = nbase + a_row;
        float4 v = make_float4(0.f, 0.f, 0.f, 0.f);
        if (n < NN) v = *(const float4*)(A + (size_t)n * 128 + kc + a_k4);
        if (relu) {
            v.x = fmaxf(v.x, 0.f); v.y = fmaxf(v.y, 0.f);
            v.z = fmaxf(v.z, 0.f); v.w = fmaxf(v.w, 0.f);
        }
        As[a_k4 + 0][a_row] = v.x; As[a_k4 + 1][a_row] = v.y;
        As[a_k4 + 2][a_row] = v.z; As[a_k4 + 3][a_row] = v.w;
#pragma unroll
        for (int r8 = 0; r8 < 8; r8++) {
            int idx = r8 * 256 + tid;
            int k = idx >> 7, jj = idx & 127;
            Bs[k][jj] = W[(kc + k) * 128 + jj];
        }
        __syncthreads();
#pragma unroll
        for (int k = 0; k < 16; k++) {
            float a[4], b[8];
#pragma unroll
            for (int i = 0; i < 4; i++) a[i] = As[k][ty * 4 + i];
#pragma unroll
            for (int jj = 0; jj < 8; jj++) b[jj] = Bs[k][tx * 8 + jj];
#pragma unroll
            for (int i = 0; i < 4; i++)
#pragma unroll
                for (int jj = 0; jj < 8; jj++) acc[i][jj] = fmaf(a[i], b[jj], acc[i][jj]);
        }
        __syncthreads();
    }
#pragma unroll
    for (int i = 0; i < 4; i++) {
        int n = nbase + ty * 4 + i;
        if (n >= NN) continue;
#pragma unroll
        for (int jj = 0; jj < 8; jj++) out[(size_t)n * 128 + tx * 8 + jj] = acc[i][jj];
    }
}

__global__ void gcn_init(const float* __restrict__ hW, const float* __restrict__ bvec,
                         const float* __restrict__ dinv, float* __restrict__ agg) {
    int idx = blockIdx.x * blockDim.x + threadIdx.x;
    if (idx >= NN * 128) return;
    int n = idx >> 7, jj = idx & 127;
    float di = dinv[n];
    agg[idx] = bvec[jj] + hW[idx] * di * di;
}

__global__ void gcn_agg(const float* __restrict__ hW, const int* __restrict__ src,
                        const int* __restrict__ dst, const float* __restrict__ dinv,
                        float* __restrict__ agg, int E) {
    int gw = (blockIdx.x * blockDim.x + threadIdx.x) >> 5;
    int lane = threadIdx.x & 31;
    if (gw >= E) return;
    int s = src[gw], d = dst[gw];
    float w = dinv[s] * dinv[d];
    float4 v = ((const float4*)(hW + (size_t)s * 128))[lane];
    float* p = agg + (size_t)d * 128 + lane * 4;
    atomicAdd(p + 0, v.x * w);
    atomicAdd(p + 1, v.y * w);
    atomicAdd(p + 2, v.z * w);
    atomicAdd(p + 3, v.w * w);
}

__global__ void gcn_gemm12(const float* __restrict__ A, const float* __restrict__ W2,
                           float* __restrict__ out12) {
    int warp = (blockIdx.x * blockDim.x + threadIdx.x) >> 5;
    int lane = threadIdx.x & 31;
    if (warp >= NN) return;
    float acc[12];
#pragma unroll
    for (int jj = 0; jj < 12; jj++) acc[jj] = 0.f;
    for (int k = lane; k < 128; k += 32) {
        float a = fmaxf(A[(size_t)warp * 128 + k], 0.f);
#pragma unroll
        for (int jj = 0; jj < 12; jj++) acc[jj] = fmaf(a, W2[k * 12 + jj], acc[jj]);
    }
#pragma unroll
    for (int jj = 0; jj < 12; jj++) {
        float v = acc[jj];
#pragma unroll
        for (int o = 16; o; o >>= 1) v += __shfl_down_sync(0xffffffffu, v, o);
        if (lane == 0) out12[(size_t)warp * 12 + jj] = v;
    }
}

__global__ void gcn_init12(const float* __restrict__ hW12, const float* __restrict__ b2,
                           const float* __restrict__ dinv, float* __restrict__ out) {
    int idx = blockIdx.x * blockDim.x + threadIdx.x;
    if (idx >= NN * 12) return;
    int n = idx / 12, jj = idx - n * 12;
    float di = dinv[n];
    out[idx] = b2[jj] + hW12[idx] * di * di;
}

__global__ void gcn_agg12(const float* __restrict__ hW12, const int* __restrict__ src,
                          const int* __restrict__ dst, const float* __restrict__ dinv,
                          float* __restrict__ out, int E) {
    int idx = blockIdx.x * blockDim.x + threadIdx.x;
    int e = idx >> 4;
    int jj = idx & 15;
    if (e >= E || jj >= 12) return;
    int s = src[e], d = dst[e];
    float w = dinv[s] * dinv[d];
    atomicAdd(&out[(size_t)d * 12 + jj], hW12[(size_t)s * 12 + jj] * w);
}

// ================= launch =================
extern "C" void kernel_launch(void* const* d_in, const int* in_sizes, int n_in,
                              void* d_out, int out_size) {
    const float* x    = (const float*)d_in[0];
    const int*   ei   = (const int*)d_in[1];
    const float* Wih0 = (const float*)d_in[2];
    const float* Whh0 = (const float*)d_in[3];
    const float* bih0 = (const float*)d_in[4];
    const float* bhh0 = (const float*)d_in[5];
    const float* Wih1 = (const float*)d_in[6];
    const float* Whh1 = (const float*)d_in[7];
    const float* bih1 = (const float*)d_in[8];
    const float* bhh1 = (const float*)d_in[9];
    const float* W0   = (const float*)d_in[10];
    const float* b0   = (const float*)d_in[11];
    const float* W1   = (const float*)d_in[12];
    const float* b1   = (const float*)d_in[13];
    const float* W2   = (const float*)d_in[14];
    const float* b2   = (const float*)d_in[15];
    float* out = (float*)d_out;

    int E = in_sizes[1] / 2;
    const int* src = ei;
    const int* dst = ei + E;

    float* S;
    cudaGetSymbolAddress((void**)&S, g_scratch);
    float* c0 = S;
    float* c1 = S + (size_t)CSLOT;
    __half* HF = (__half*)(S + 2 * (size_t)CSLOT);
    __half* h0[2] = { HF + 0 * (size_t)NH, HF + 1 * (size_t)NH };
    __half* h1[2] = { HF + 2 * (size_t)NH, HF + 3 * (size_t)NH };
    float* hfin = S + 2 * (size_t)CSLOT + 2 * (size_t)NH;
    float* hw   = hfin + (size_t)NH;
    float* agg  = hw + (size_t)NH;
    float* dinv = agg + (size_t)NH;
    __half* Q = (__half*)(dinv + 65536);
    __half* B0  = Q;  Q += 8 * 144 * 64;
    __half* B1  = Q;  Q += 8 * 272 * 64;
    __half* Bt0 = Q;  Q += 8 * 144 * 64;
    __half* xp  = Q;  Q += (size_t)12 * NN * 16;
    __half* on  = Q;  Q += (size_t)NN * 16;

    zero_k<<<(2 * CSLOT + 255) / 256, 256>>>(S, 2 * CSLOT);
    prep_aug<<<(13 * NN * 16 + 255) / 256, 256>>>(x, xp, on);
    prep_B0<<<(8 * 144 * 64 + 255) / 256, 256>>>(Whh0, Wih0, bih0, bhh0, B0);
    prep_B1<<<(8 * 272 * 64 + 255) / 256, 256>>>(Wih1, Whh1, bih1, bhh1, B1);
    prep_B1t0<<<(8 * 144 * 64 + 255) / 256, 256>>>(Wih1, bih1, bhh1, Bt0);

    const int SM9  = 144 * 144 + 16 * 6144;   // 20736 + 98304 = 119040
    const int SM17 = 272 * 144 + 16 * 6144;   // 39168 + 98304 = 137472
    cudaFuncSetAttribute(lstm_mma<9>,  cudaFuncAttributeMaxDynamicSharedMemorySize, SM9);
    cudaFuncSetAttribute(lstm_mma<17>, cudaFuncAttributeMaxDynamicSharedMemorySize, SM17);

    dim3 lg(18, 8);
    int p = 0;
    for (int t = 0; t < TT; t++) {
        lstm_mma<9><<<lg, 512, SM9>>>(
            h0[p], (const __half*)nullptr, xp + (size_t)t * NN * 16,
            B0, t == 0 ? 8 : 0, c0, h0[1 - p]);
        if (t == 0) {
            lstm_mma<9><<<lg, 512, SM9>>>(
                h0[1 - p], (const __half*)nullptr, on, Bt0, 0, c1, h1[1 - p]);
        } else {
            lstm_mma<17><<<lg, 512, SM17>>>(
                h0[1 - p], h1[p], on, B1, 0, c1, h1[1 - p]);
        }
        p ^= 1;
    }
    recon_h<<<(NH + 255) / 256, 256>>>(h1[p], hfin);

    deg_init<<<(NN + 255) / 256, 256>>>(dinv);
    deg_count<<<(E + 255) / 256, 256>>>(dst, dinv, E);
    deg_rsqrt<<<(NN + 255) / 256, 256>>>(dinv);

    gcn_gemm<<<(NN + 63) / 64, 256>>>(hfin, W0, hw, 0);
    gcn_init<<<(NN * 128 + 255) / 256, 256>>>(hw, b0, dinv, agg);
    gcn_agg<<<(E + 7) / 8, 256>>>(hw, src, dst, dinv, agg, E);
    gcn_gemm<<<(NN + 63) / 64, 256>>>(agg, W1, hw, 1);
    gcn_init<<<(NN * 128 + 255) / 256, 256>>>(hw, b1, dinv, agg);
    gcn_agg<<<(E + 7) / 8, 256>>>(hw, src, dst, dinv, agg, E);
    gcn_gemm12<<<(NN * 32 + 255) / 256, 256>>>(agg, W2, hw);
    gcn_init12<<<(NN * 12 + 255) / 256, 256>>>(hw, b2, dinv, out);
    gcn_agg12<<<((size_t)E * 16 + 255) / 256, 256>>>(hw, src, dst, dinv, out, E);
}